// round 16
// baseline (speedup 1.0000x reference)
#include <cuda_runtime.h>
#include <cuda_fp16.h>
#include <cstdint>
#include <cstddef>

// ============================================================================
// Problem constants
// ============================================================================
#define R_DIM 32
#define I_DIM 256
#define O_DIM 256
#define K_MAIN (R_DIM * I_DIM)   // 8192
#define NCH 129                  // 128 main chunks + 1 bias chunk
#define M_TILE 128
#define N_TILE 128
#define THREADS 256

// SMEM: x tile fp16 (128 rows * 512B, swizzled) + e fp16 [128][34]
#define XOFF 0
#define E2OFF 65536
#define SMEM_TOTAL (E2OFF + 8704)      // 74240 -> 2 CTAs/SM

// Packed B fragments, mma.sync-native layout (sequential chunks):
// g_P[oh][j][ks][q][lane] : uint4.  oh = 64-wide O block (4), j = K chunk (129),
// ks = k-step (4), q = reg quad (4), lane = 0..31.
// Padded by 2 ks-blocks so the +2ks L1 prefetch never leaves the array.
#define P_U4_PER_KS  128
#define P_U4_PER_J   (4 * P_U4_PER_KS)
#define P_U4_PER_OH  (NCH * P_U4_PER_J)
__device__ __align__(128) uint4 g_P[4 * P_U4_PER_OH + 2 * P_U4_PER_KS];

// ============================================================================
// PTX helpers (plain sm_100-safe)
// ============================================================================
__device__ __forceinline__ uint32_t smem_u32(const void* p) {
    uint32_t a;
    asm("{ .reg .u64 t; cvta.to.shared.u64 t, %1; cvt.u32.u64 %0, t; }"
        : "=r"(a) : "l"(p));
    return a;
}

#define LDSM_X4(r0, r1, r2, r3, addr) \
    asm volatile("ldmatrix.sync.aligned.m8n8.x4.shared.b16 {%0,%1,%2,%3}, [%4];" \
        : "=r"(r0), "=r"(r1), "=r"(r2), "=r"(r3) : "r"(addr))

#define MMA16816(d, a, b0, b1) \
    asm volatile("mma.sync.aligned.m16n8k16.row.col.f32.f16.f16.f32 " \
        "{%0,%1,%2,%3}, {%4,%5,%6,%7}, {%8,%9}, {%0,%1,%2,%3};" \
        : "+f"((d)[0]), "+f"((d)[1]), "+f"((d)[2]), "+f"((d)[3]) \
        : "r"((a)[0]), "r"((a)[1]), "r"((a)[2]), "r"((a)[3]), \
          "r"(b0), "r"(b1))

#define PREFETCH_L1(addr) \
    asm volatile("prefetch.global.L1 [%0];" :: "l"(addr))

__device__ __forceinline__ uint32_t hmul2_u(uint32_t a, uint32_t s) {
    __half2 r = __hmul2(*reinterpret_cast<__half2*>(&a),
                        *reinterpret_cast<__half2*>(&s));
    return *reinterpret_cast<uint32_t*>(&r);
}

// ============================================================================
// Prep kernel: W [R,O,I] fp32 + b [R,O] fp32 -> fragment-packed fp16 g_P
// ============================================================================
__global__ void LinearKG_prep_kernel(const float* __restrict__ W,
                                     const float* __restrict__ b) {
    int idx = blockIdx.x * blockDim.x + threadIdx.x;        // u32 index
    if (idx >= 4 * P_U4_PER_OH * 4) return;
    int c = idx & 3;
    int u4 = idx >> 2;
    int lane = u4 & 31;
    int q = (u4 >> 5) & 3;
    int rest = u4 >> 7;
    int ks = rest & 3;
    rest >>= 2;
    int j = rest % NCH;
    int oh = rest / NCH;

    int reg = q * 4 + c;
    int nt = reg >> 1;
    int bb = reg & 1;
    int o = oh * 64 + nt * 8 + (lane >> 2);
    int k = j * 64 + ks * 16 + bb * 8 + (lane & 3) * 2;

    float v0, v1;
    if (k < K_MAIN) {
        int r = k >> 8, i = k & 255;
        const float* wp = W + ((size_t)r * O_DIM + o) * I_DIM + i;
        v0 = wp[0];
        v1 = wp[1];
    } else {
        int r = k - K_MAIN;
        v0 = (r < R_DIM) ? b[r * O_DIM + o] : 0.0f;
        v1 = (r + 1 < R_DIM) ? b[(r + 1) * O_DIM + o] : 0.0f;
    }
    __half2 h = __floats2half2_rn(v0, v1);
    reinterpret_cast<uint32_t*>(g_P)[idx] = *reinterpret_cast<uint32_t*>(&h);
}

// ============================================================================
// Main fused GEMM: y[128x128 tile] = A @ B^T.
// R14 structure verbatim (on-the-fly A, register-streamed B, no mainloop
// barriers, jg-outer unrolled 16-ks body, 8 warps 4Mx2N, 2 CTAs/SM,
// tail-wave-free grid) + prefetch.global.L1 of the ks+2 B block so the
// leading warp of each M-group hits L1 instead of stalling on L2.
// ============================================================================
__global__ void __launch_bounds__(THREADS, 2)
LinearKG_main_kernel(const float* __restrict__ xg,
                     const float* __restrict__ eg,
                     float* __restrict__ out,
                     int n_nodes, int workers, int extras) {
    extern __shared__ __align__(1024) char smem[];
    const uint32_t sb = smem_u32(smem);
    const int tid = threadIdx.x;
    const int wid = tid >> 5;
    const int lid = tid & 31;
    const int warpM = (wid & 3) << 5;    // 0,32,64,96
    const int warpNh = wid >> 2;         // 0,1 -> 64-wide O half

    // ---- per-thread invariants (tile-independent) ----
    const int g = lid >> 3;
    const int l7 = lid & 7;
    const int a_moff = (g & 1) * 8;
    const int a_koff = g >> 1;

    uint32_t aBase[2]; int aXor[2];
    #pragma unroll
    for (int mt = 0; mt < 2; mt++) {
        int mrow = warpM + mt * 16 + a_moff + l7;
        aBase[mt] = sb + XOFF + mrow * 512;
        aXor[mt] = mrow & 7;
    }
    const int frow = lid >> 2;
    const int fcol = (lid & 3) * 2;
    const int erow0 = (warpM + frow) * 34;
    const int erow1 = (warpM + 8 + frow) * 34;
    const __half* e2h = reinterpret_cast<const __half*>(smem + E2OFF);

    const int my_tiles = (blockIdx.x < (unsigned)extras) ? 2 : 1;
    int t = blockIdx.x;

    for (int itile = 0; itile < my_tiles; itile++, t += workers) {
        const int row_base = (t >> 1) * M_TILE;
        const int ohh = t & 1;               // O half

        // ---- fill x tile (fp32 -> fp16, swizzled) + e tile ----
        __syncthreads();    // WAR vs previous tile's readers
        {
            const float4* x4 = reinterpret_cast<const float4*>(xg);
            #pragma unroll
            for (int it = 0; it < 16; it++) {
                int v = tid + it * THREADS;          // 0..4095
                int row = v >> 5, c = v & 31;
                int gr = row_base + row;
                float4 f0 = make_float4(0.f, 0.f, 0.f, 0.f), f1 = f0;
                if (gr < n_nodes) {
                    f0 = x4[(size_t)gr * 64 + c * 2];
                    f1 = x4[(size_t)gr * 64 + c * 2 + 1];
                }
                __half2 h0 = __floats2half2_rn(f0.x, f0.y);
                __half2 h1 = __floats2half2_rn(f0.z, f0.w);
                __half2 h2 = __floats2half2_rn(f1.x, f1.y);
                __half2 h3 = __floats2half2_rn(f1.z, f1.w);
                uint4 u;
                u.x = *reinterpret_cast<uint32_t*>(&h0);
                u.y = *reinterpret_cast<uint32_t*>(&h1);
                u.z = *reinterpret_cast<uint32_t*>(&h2);
                u.w = *reinterpret_cast<uint32_t*>(&h3);
                *reinterpret_cast<uint4*>(smem + XOFF + row * 512 +
                                          ((c ^ (row & 7)) << 4)) = u;
            }
            __half* e2w = reinterpret_cast<__half*>(smem + E2OFF);
            #pragma unroll
            for (int it = 0; it < 16; it++) {
                int v = tid + it * THREADS;          // 0..4095
                int row = v >> 5, r = v & 31;
                int gr = row_base + row;
                float ev = (gr < n_nodes) ? eg[(size_t)gr * R_DIM + r] : 0.0f;
                e2w[row * 34 + r] = __float2half(ev);
            }
        }
        __syncthreads();   // publish x/e

        // ---- B fragment stream pointer (uint4 units), linear walk ----
        const int oh = ohh * 2 + warpNh;             // 0..3
        const uint4* __restrict__ pp = g_P + (size_t)oh * P_U4_PER_OH + lid;

        float acc[2][8][4];
        #pragma unroll
        for (int mt = 0; mt < 2; mt++)
            #pragma unroll
            for (int nt = 0; nt < 8; nt++)
                #pragma unroll
                for (int q = 0; q < 4; q++) acc[mt][nt][q] = 0.0f;

        // prologue: prefetch B frags for (j=0, ks=0)
        uint4 nb0 = pp[0], nb1 = pp[32], nb2 = pp[64], nb3 = pp[96];
        pp += P_U4_PER_KS;

        // ---- main loop: 32 r-groups x 4 chunks x 4 ks, body unrolled ----
        #pragma unroll 1
        for (int jg = 0; jg < 32; jg++) {
            uint32_t ez0[2], ez1[2];
            #pragma unroll
            for (int mt = 0; mt < 2; mt++) {
                __half h0 = e2h[erow0 + mt * 16 * 34 + jg];
                __half h1 = e2h[erow1 + mt * 16 * 34 + jg];
                __half2 p0 = __half2half2(h0);
                __half2 p1 = __half2half2(h1);
                ez0[mt] = *reinterpret_cast<uint32_t*>(&p0);
                ez1[mt] = *reinterpret_cast<uint32_t*>(&p1);
            }
            #pragma unroll
            for (int jj = 0; jj < 4; jj++) {
                const int kcA = jj * 8;
                #pragma unroll
                for (int ks = 0; ks < 4; ks++) {
                    uint4 c0 = nb0, c1 = nb1, c2 = nb2, c3 = nb3;
                    nb0 = pp[0]; nb1 = pp[32]; nb2 = pp[64]; nb3 = pp[96];
                    // warm L1 for the ks+2 block (zero registers)
                    PREFETCH_L1(pp + P_U4_PER_KS);
                    PREFETCH_L1(pp + P_U4_PER_KS + 32);
                    PREFETCH_L1(pp + P_U4_PER_KS + 64);
                    PREFETCH_L1(pp + P_U4_PER_KS + 96);
                    pp += P_U4_PER_KS;

                    uint32_t a[2][4];
                    #pragma unroll
                    for (int mt = 0; mt < 2; mt++) {
                        int kc = kcA + ks * 2 + a_koff;
                        uint32_t ad = aBase[mt] + ((kc ^ aXor[mt]) << 4);
                        LDSM_X4(a[mt][0], a[mt][1], a[mt][2], a[mt][3], ad);
                        a[mt][0] = hmul2_u(a[mt][0], ez0[mt]);
                        a[mt][1] = hmul2_u(a[mt][1], ez1[mt]);
                        a[mt][2] = hmul2_u(a[mt][2], ez0[mt]);
                        a[mt][3] = hmul2_u(a[mt][3], ez1[mt]);
                    }
                    #pragma unroll
                    for (int mt = 0; mt < 2; mt++) {
                        MMA16816(acc[mt][0], a[mt], c0.x, c0.y);
                        MMA16816(acc[mt][1], a[mt], c0.z, c0.w);
                        MMA16816(acc[mt][2], a[mt], c1.x, c1.y);
                        MMA16816(acc[mt][3], a[mt], c1.z, c1.w);
                        MMA16816(acc[mt][4], a[mt], c2.x, c2.y);
                        MMA16816(acc[mt][5], a[mt], c2.z, c2.w);
                        MMA16816(acc[mt][6], a[mt], c3.x, c3.y);
                        MMA16816(acc[mt][7], a[mt], c3.z, c3.w);
                    }
                }
            }
        }

        // ---- bias chunk (j=128): A[m,k] = e[m,k], ksteps 0..1 ----
        {
            #pragma unroll
            for (int ks = 0; ks < 2; ks++) {
                uint4 c0, c1, c2, c3;
                if (ks == 0) { c0 = nb0; c1 = nb1; c2 = nb2; c3 = nb3; }
                else         { c0 = pp[0]; c1 = pp[32]; c2 = pp[64]; c3 = pp[96]; }

                const int k0 = ks * 16 + fcol;
                uint32_t a[2][4];
                #pragma unroll
                for (int mt = 0; mt < 2; mt++) {
                    a[mt][0] = *reinterpret_cast<const uint32_t*>(
                        e2h + erow0 + mt * 16 * 34 + k0);
                    a[mt][1] = *reinterpret_cast<const uint32_t*>(
                        e2h + erow1 + mt * 16 * 34 + k0);
                    a[mt][2] = *reinterpret_cast<const uint32_t*>(
                        e2h + erow0 + mt * 16 * 34 + k0 + 8);
                    a[mt][3] = *reinterpret_cast<const uint32_t*>(
                        e2h + erow1 + mt * 16 * 34 + k0 + 8);
                }
                #pragma unroll
                for (int mt = 0; mt < 2; mt++) {
                    MMA16816(acc[mt][0], a[mt], c0.x, c0.y);
                    MMA16816(acc[mt][1], a[mt], c0.z, c0.w);
                    MMA16816(acc[mt][2], a[mt], c1.x, c1.y);
                    MMA16816(acc[mt][3], a[mt], c1.z, c1.w);
                    MMA16816(acc[mt][4], a[mt], c2.x, c2.y);
                    MMA16816(acc[mt][5], a[mt], c2.z, c2.w);
                    MMA16816(acc[mt][6], a[mt], c3.x, c3.y);
                    MMA16816(acc[mt][7], a[mt], c3.z, c3.w);
                }
            }
        }

        // ---- epilogue: store fp32 accumulators ----
        const int o_col0 = ohh * N_TILE + warpNh * 64;
        #pragma unroll
        for (int mt = 0; mt < 2; mt++) {
            int r0 = row_base + warpM + mt * 16 + frow;
            int r1 = r0 + 8;
            #pragma unroll
            for (int nt = 0; nt < 8; nt++) {
                int col = o_col0 + nt * 8 + fcol;
                if (r0 < n_nodes) {
                    float2 v = make_float2(acc[mt][nt][0], acc[mt][nt][1]);
                    *reinterpret_cast<float2*>(out + (size_t)r0 * O_DIM + col) = v;
                }
                if (r1 < n_nodes) {
                    float2 v = make_float2(acc[mt][nt][2], acc[mt][nt][3]);
                    *reinterpret_cast<float2*>(out + (size_t)r1 * O_DIM + col) = v;
                }
            }
        }
    }
}

// ============================================================================
// Launch
// ============================================================================
extern "C" void kernel_launch(void* const* d_in, const int* in_sizes, int n_in,
                              void* d_out, int out_size) {
    const float* x = (const float*)d_in[0];   // [N, 256]
    const float* e = (const float*)d_in[1];   // [N, 32]
    const float* W = (const float*)d_in[2];   // [32, 256, 256]
    const float* b = (const float*)d_in[3];   // [32, 256]
    float* out = (float*)d_out;               // [N, 256]

    int n_nodes = in_sizes[0] / I_DIM;

    int prep_total = 4 * P_U4_PER_OH * 4;     // u32 elements
    LinearKG_prep_kernel<<<(prep_total + 255) / 256, 256>>>(W, b);

    // tail-wave-free worker count: slots = SMs * 2 CTAs/SM
    static int num_sms = 0;
    if (num_sms == 0) {
        cudaDeviceGetAttribute(&num_sms, cudaDevAttrMultiProcessorCount, 0);
        if (num_sms <= 0) num_sms = 148;
    }
    int slots = num_sms * 2;
    int tiles_m = (n_nodes + M_TILE - 1) / M_TILE;
    int total = tiles_m * 2;                  // x2 O halves
    int workers = (total > slots) ? (total / slots) * slots : total;
    int extras = total - workers;

    cudaFuncSetAttribute(LinearKG_main_kernel,
                         cudaFuncAttributeMaxDynamicSharedMemorySize, SMEM_TOTAL);
    LinearKG_main_kernel<<<workers, THREADS, SMEM_TOTAL>>>(
        x, e, out, n_nodes, workers, extras);
}

// round 17
// speedup vs baseline: 1.0625x; 1.0625x over previous
#include <cuda_runtime.h>
#include <cuda_fp16.h>
#include <cstdint>
#include <cstddef>

// ============================================================================
// Problem constants
// ============================================================================
#define R_DIM 32
#define I_DIM 256
#define O_DIM 256
#define K_MAIN (R_DIM * I_DIM)   // 8192
#define NCH 129                  // 128 main chunks + 1 bias chunk
#define M_TILE 128
#define N_TILE 128
#define THREADS 256

// SMEM: x tile fp16 (128 rows * 512B, swizzled) + e fp16 [128][34]
#define XOFF 0
#define E2OFF 65536
#define SMEM_TOTAL (E2OFF + 8704)      // 74240 -> 2 CTAs/SM

// Packed B fragments, mma.sync-native layout (sequential chunks):
// g_P[oh][j][ks][q][lane] : uint4.  oh = 64-wide O block (4), j = K chunk (129),
// ks = k-step (4), q = reg quad (4), lane = 0..31.
#define P_U4_PER_KS  128
#define P_U4_PER_J   (4 * P_U4_PER_KS)
#define P_U4_PER_OH  (NCH * P_U4_PER_J)
__device__ __align__(128) uint4 g_P[4 * P_U4_PER_OH];   // 4.2 MB, L2-resident

// ============================================================================
// PTX helpers (plain sm_100-safe)
// ============================================================================
__device__ __forceinline__ uint32_t smem_u32(const void* p) {
    uint32_t a;
    asm("{ .reg .u64 t; cvta.to.shared.u64 t, %1; cvt.u32.u64 %0, t; }"
        : "=r"(a) : "l"(p));
    return a;
}

#define LDSM_X4(r0, r1, r2, r3, addr) \
    asm volatile("ldmatrix.sync.aligned.m8n8.x4.shared.b16 {%0,%1,%2,%3}, [%4];" \
        : "=r"(r0), "=r"(r1), "=r"(r2), "=r"(r3) : "r"(addr))

#define MMA16816(d, a, b0, b1) \
    asm volatile("mma.sync.aligned.m16n8k16.row.col.f32.f16.f16.f32 " \
        "{%0,%1,%2,%3}, {%4,%5,%6,%7}, {%8,%9}, {%0,%1,%2,%3};" \
        : "+f"((d)[0]), "+f"((d)[1]), "+f"((d)[2]), "+f"((d)[3]) \
        : "r"((a)[0]), "r"((a)[1]), "r"((a)[2]), "r"((a)[3]), \
          "r"(b0), "r"(b1))

__device__ __forceinline__ uint32_t hmul2_u(uint32_t a, uint32_t s) {
    __half2 r = __hmul2(*reinterpret_cast<__half2*>(&a),
                        *reinterpret_cast<__half2*>(&s));
    return *reinterpret_cast<uint32_t*>(&r);
}

// ============================================================================
// Prep kernel: W [R,O,I] fp32 + b [R,O] fp32 -> fragment-packed fp16 g_P
// ============================================================================
__global__ void LinearKG_prep_kernel(const float* __restrict__ W,
                                     const float* __restrict__ b) {
    int idx = blockIdx.x * blockDim.x + threadIdx.x;        // u32 index
    if (idx >= 4 * P_U4_PER_OH * 4) return;
    int c = idx & 3;
    int u4 = idx >> 2;
    int lane = u4 & 31;
    int q = (u4 >> 5) & 3;
    int rest = u4 >> 7;
    int ks = rest & 3;
    rest >>= 2;
    int j = rest % NCH;
    int oh = rest / NCH;

    int reg = q * 4 + c;
    int nt = reg >> 1;
    int bb = reg & 1;
    int o = oh * 64 + nt * 8 + (lane >> 2);
    int k = j * 64 + ks * 16 + bb * 8 + (lane & 3) * 2;

    float v0, v1;
    if (k < K_MAIN) {
        int r = k >> 8, i = k & 255;
        const float* wp = W + ((size_t)r * O_DIM + o) * I_DIM + i;
        v0 = wp[0];
        v1 = wp[1];
    } else {
        int r = k - K_MAIN;
        v0 = (r < R_DIM) ? b[r * O_DIM + o] : 0.0f;
        v1 = (r + 1 < R_DIM) ? b[(r + 1) * O_DIM + o] : 0.0f;
    }
    __half2 h = __floats2half2_rn(v0, v1);
    reinterpret_cast<uint32_t*>(g_P)[idx] = *reinterpret_cast<uint32_t*>(&h);
}

// ============================================================================
// Main fused GEMM: y[128x128 tile] = A @ B^T.
// Final converged design (R14): on-the-fly A (ldsm + e-rescale from smem),
// register-streamed B from L2-resident fragment-packed g_P, NO mainloop
// barriers, jg-outer loop with fully unrolled 16-ks body, 8 warps 4Mx2N,
// 2 CTAs/SM, tail-wave-free grid (first `extras` workers take 2 tiles).
// ============================================================================
__global__ void __launch_bounds__(THREADS, 2)
LinearKG_main_kernel(const float* __restrict__ xg,
                     const float* __restrict__ eg,
                     float* __restrict__ out,
                     int n_nodes, int workers, int extras) {
    extern __shared__ __align__(1024) char smem[];
    const uint32_t sb = smem_u32(smem);
    const int tid = threadIdx.x;
    const int wid = tid >> 5;
    const int lid = tid & 31;
    const int warpM = (wid & 3) << 5;    // 0,32,64,96
    const int warpNh = wid >> 2;         // 0,1 -> 64-wide O half

    // ---- per-thread invariants (tile-independent) ----
    const int g = lid >> 3;
    const int l7 = lid & 7;
    const int a_moff = (g & 1) * 8;
    const int a_koff = g >> 1;

    uint32_t aBase[2]; int aXor[2];
    #pragma unroll
    for (int mt = 0; mt < 2; mt++) {
        int mrow = warpM + mt * 16 + a_moff + l7;
        aBase[mt] = sb + XOFF + mrow * 512;
        aXor[mt] = mrow & 7;
    }
    const int frow = lid >> 2;
    const int fcol = (lid & 3) * 2;
    const int erow0 = (warpM + frow) * 34;
    const int erow1 = (warpM + 8 + frow) * 34;
    const __half* e2h = reinterpret_cast<const __half*>(smem + E2OFF);

    const int my_tiles = (blockIdx.x < (unsigned)extras) ? 2 : 1;
    int t = blockIdx.x;

    for (int itile = 0; itile < my_tiles; itile++, t += workers) {
        const int row_base = (t >> 1) * M_TILE;
        const int ohh = t & 1;               // O half

        // ---- fill x tile (fp32 -> fp16, swizzled) + e tile ----
        __syncthreads();    // WAR vs previous tile's readers
        {
            const float4* x4 = reinterpret_cast<const float4*>(xg);
            #pragma unroll
            for (int it = 0; it < 16; it++) {
                int v = tid + it * THREADS;          // 0..4095
                int row = v >> 5, c = v & 31;
                int gr = row_base + row;
                float4 f0 = make_float4(0.f, 0.f, 0.f, 0.f), f1 = f0;
                if (gr < n_nodes) {
                    f0 = x4[(size_t)gr * 64 + c * 2];
                    f1 = x4[(size_t)gr * 64 + c * 2 + 1];
                }
                __half2 h0 = __floats2half2_rn(f0.x, f0.y);
                __half2 h1 = __floats2half2_rn(f0.z, f0.w);
                __half2 h2 = __floats2half2_rn(f1.x, f1.y);
                __half2 h3 = __floats2half2_rn(f1.z, f1.w);
                uint4 u;
                u.x = *reinterpret_cast<uint32_t*>(&h0);
                u.y = *reinterpret_cast<uint32_t*>(&h1);
                u.z = *reinterpret_cast<uint32_t*>(&h2);
                u.w = *reinterpret_cast<uint32_t*>(&h3);
                *reinterpret_cast<uint4*>(smem + XOFF + row * 512 +
                                          ((c ^ (row & 7)) << 4)) = u;
            }
            __half* e2w = reinterpret_cast<__half*>(smem + E2OFF);
            #pragma unroll
            for (int it = 0; it < 16; it++) {
                int v = tid + it * THREADS;          // 0..4095
                int row = v >> 5, r = v & 31;
                int gr = row_base + row;
                float ev = (gr < n_nodes) ? eg[(size_t)gr * R_DIM + r] : 0.0f;
                e2w[row * 34 + r] = __float2half(ev);
            }
        }
        __syncthreads();   // publish x/e

        // ---- B fragment stream pointer (uint4 units), linear walk ----
        const int oh = ohh * 2 + warpNh;             // 0..3
        const uint4* __restrict__ pp = g_P + (size_t)oh * P_U4_PER_OH + lid;

        float acc[2][8][4];
        #pragma unroll
        for (int mt = 0; mt < 2; mt++)
            #pragma unroll
            for (int nt = 0; nt < 8; nt++)
                #pragma unroll
                for (int q = 0; q < 4; q++) acc[mt][nt][q] = 0.0f;

        // prologue: prefetch B frags for (j=0, ks=0)
        uint4 nb0 = pp[0], nb1 = pp[32], nb2 = pp[64], nb3 = pp[96];
        pp += P_U4_PER_KS;

        // ---- main loop: 32 r-groups x 4 chunks x 4 ks, body unrolled ----
        #pragma unroll 1
        for (int jg = 0; jg < 32; jg++) {
            uint32_t ez0[2], ez1[2];
            #pragma unroll
            for (int mt = 0; mt < 2; mt++) {
                __half h0 = e2h[erow0 + mt * 16 * 34 + jg];
                __half h1 = e2h[erow1 + mt * 16 * 34 + jg];
                __half2 p0 = __half2half2(h0);
                __half2 p1 = __half2half2(h1);
                ez0[mt] = *reinterpret_cast<uint32_t*>(&p0);
                ez1[mt] = *reinterpret_cast<uint32_t*>(&p1);
            }
            #pragma unroll
            for (int jj = 0; jj < 4; jj++) {
                const int kcA = jj * 8;
                #pragma unroll
                for (int ks = 0; ks < 4; ks++) {
                    uint4 c0 = nb0, c1 = nb1, c2 = nb2, c3 = nb3;
                    nb0 = pp[0]; nb1 = pp[32]; nb2 = pp[64]; nb3 = pp[96];
                    pp += P_U4_PER_KS;

                    uint32_t a[2][4];
                    #pragma unroll
                    for (int mt = 0; mt < 2; mt++) {
                        int kc = kcA + ks * 2 + a_koff;
                        uint32_t ad = aBase[mt] + ((kc ^ aXor[mt]) << 4);
                        LDSM_X4(a[mt][0], a[mt][1], a[mt][2], a[mt][3], ad);
                        a[mt][0] = hmul2_u(a[mt][0], ez0[mt]);
                        a[mt][1] = hmul2_u(a[mt][1], ez1[mt]);
                        a[mt][2] = hmul2_u(a[mt][2], ez0[mt]);
                        a[mt][3] = hmul2_u(a[mt][3], ez1[mt]);
                    }
                    #pragma unroll
                    for (int mt = 0; mt < 2; mt++) {
                        MMA16816(acc[mt][0], a[mt], c0.x, c0.y);
                        MMA16816(acc[mt][1], a[mt], c0.z, c0.w);
                        MMA16816(acc[mt][2], a[mt], c1.x, c1.y);
                        MMA16816(acc[mt][3], a[mt], c1.z, c1.w);
                        MMA16816(acc[mt][4], a[mt], c2.x, c2.y);
                        MMA16816(acc[mt][5], a[mt], c2.z, c2.w);
                        MMA16816(acc[mt][6], a[mt], c3.x, c3.y);
                        MMA16816(acc[mt][7], a[mt], c3.z, c3.w);
                    }
                }
            }
        }

        // ---- bias chunk (j=128): A[m,k] = e[m,k], ksteps 0..1 ----
        {
            #pragma unroll
            for (int ks = 0; ks < 2; ks++) {
                uint4 c0, c1, c2, c3;
                if (ks == 0) { c0 = nb0; c1 = nb1; c2 = nb2; c3 = nb3; }
                else         { c0 = pp[0]; c1 = pp[32]; c2 = pp[64]; c3 = pp[96]; }

                const int k0 = ks * 16 + fcol;
                uint32_t a[2][4];
                #pragma unroll
                for (int mt = 0; mt < 2; mt++) {
                    a[mt][0] = *reinterpret_cast<const uint32_t*>(
                        e2h + erow0 + mt * 16 * 34 + k0);
                    a[mt][1] = *reinterpret_cast<const uint32_t*>(
                        e2h + erow1 + mt * 16 * 34 + k0);
                    a[mt][2] = *reinterpret_cast<const uint32_t*>(
                        e2h + erow0 + mt * 16 * 34 + k0 + 8);
                    a[mt][3] = *reinterpret_cast<const uint32_t*>(
                        e2h + erow1 + mt * 16 * 34 + k0 + 8);
                }
                #pragma unroll
                for (int mt = 0; mt < 2; mt++) {
                    MMA16816(acc[mt][0], a[mt], c0.x, c0.y);
                    MMA16816(acc[mt][1], a[mt], c0.z, c0.w);
                    MMA16816(acc[mt][2], a[mt], c1.x, c1.y);
                    MMA16816(acc[mt][3], a[mt], c1.z, c1.w);
                    MMA16816(acc[mt][4], a[mt], c2.x, c2.y);
                    MMA16816(acc[mt][5], a[mt], c2.z, c2.w);
                    MMA16816(acc[mt][6], a[mt], c3.x, c3.y);
                    MMA16816(acc[mt][7], a[mt], c3.z, c3.w);
                }
            }
        }

        // ---- epilogue: store fp32 accumulators ----
        const int o_col0 = ohh * N_TILE + warpNh * 64;
        #pragma unroll
        for (int mt = 0; mt < 2; mt++) {
            int r0 = row_base + warpM + mt * 16 + frow;
            int r1 = r0 + 8;
            #pragma unroll
            for (int nt = 0; nt < 8; nt++) {
                int col = o_col0 + nt * 8 + fcol;
                if (r0 < n_nodes) {
                    float2 v = make_float2(acc[mt][nt][0], acc[mt][nt][1]);
                    *reinterpret_cast<float2*>(out + (size_t)r0 * O_DIM + col) = v;
                }
                if (r1 < n_nodes) {
                    float2 v = make_float2(acc[mt][nt][2], acc[mt][nt][3]);
                    *reinterpret_cast<float2*>(out + (size_t)r1 * O_DIM + col) = v;
                }
            }
        }
    }
}

// ============================================================================
// Launch
// ============================================================================
extern "C" void kernel_launch(void* const* d_in, const int* in_sizes, int n_in,
                              void* d_out, int out_size) {
    const float* x = (const float*)d_in[0];   // [N, 256]
    const float* e = (const float*)d_in[1];   // [N, 32]
    const float* W = (const float*)d_in[2];   // [32, 256, 256]
    const float* b = (const float*)d_in[3];   // [32, 256]
    float* out = (float*)d_out;               // [N, 256]

    int n_nodes = in_sizes[0] / I_DIM;

    int prep_total = 4 * P_U4_PER_OH * 4;     // u32 elements
    LinearKG_prep_kernel<<<(prep_total + 255) / 256, 256>>>(W, b);

    // tail-wave-free worker count: slots = SMs * 2 CTAs/SM
    static int num_sms = 0;
    if (num_sms == 0) {
        cudaDeviceGetAttribute(&num_sms, cudaDevAttrMultiProcessorCount, 0);
        if (num_sms <= 0) num_sms = 148;
    }
    int slots = num_sms * 2;
    int tiles_m = (n_nodes + M_TILE - 1) / M_TILE;
    int total = tiles_m * 2;                  // x2 O halves
    int workers = (total > slots) ? (total / slots) * slots : total;
    int extras = total - workers;

    cudaFuncSetAttribute(LinearKG_main_kernel,
                         cudaFuncAttributeMaxDynamicSharedMemorySize, SMEM_TOTAL);
    LinearKG_main_kernel<<<workers, THREADS, SMEM_TOTAL>>>(
        x, e, out, n_nodes, workers, extras);
}